// round 2
// baseline (speedup 1.0000x reference)
#include <cuda_runtime.h>
#include <cstdint>

// Problem shape (fixed by the reference)
#define BATCH 8
#define SEQ   2048
#define DIM   512
#define MQKV  (BATCH*SEQ)   // 16384

// Scratch (device globals: allocation-free per harness rules)
__device__ float g_Q[BATCH*SEQ*DIM];                 // 32 MB
__device__ float g_K[BATCH*SEQ*DIM];                 // 32 MB
__device__ float g_V[BATCH*SEQ*DIM];                 // 32 MB
__device__ float g_S[(size_t)BATCH*SEQ*SEQ];         // 128 MB

// ---------------------------------------------------------------------------
// 3xTF32 tensor-core GEMM, 128x128x16 tile, 256 threads (8 warps as 2x4),
// warp tile 64x32 of m16n8k8 tf32 MMAs, double-buffered smem, hi/lo split
// computed at smem-store time. Error ~2^-22 relative: fp32-grade output.
//   TRANS_B = true : B is [N,K] row-major (C = A * B^T)
//   TRANS_B = false: B is [K,N] row-major (C = A * B), transposed on store
// ---------------------------------------------------------------------------
#define BM 128
#define BN 128
#define BK 16
#define SA 20                      // padded row stride (conflict-free: 20m+k)
#define TILE_F (128*SA)            // 2560 floats per tile array
#define SMEM_FLOATS (2*4*TILE_F)   // 2 buffers x {A_hi,A_lo,B_hi,B_lo}
#define SMEM_BYTES (SMEM_FLOATS*4) // 81920 bytes

__device__ __forceinline__ uint32_t f2u(float x) { return __float_as_uint(x); }

__device__ __forceinline__ void split_tf32(float x, float& hi, float& lo)
{
    uint32_t h;
    asm("cvt.rna.tf32.f32 %0, %1;" : "=r"(h) : "f"(x));
    float hf = __uint_as_float(h);
    float l  = x - hf;                     // exact (Sterbenz-style)
    uint32_t lw;
    asm("cvt.rna.tf32.f32 %0, %1;" : "=r"(lw) : "f"(l));
    hi = hf;
    lo = __uint_as_float(lw);
}

__device__ __forceinline__ void mma8(float* c, const uint32_t* a, const uint32_t* b)
{
    asm volatile(
        "mma.sync.aligned.m16n8k8.row.col.f32.tf32.tf32.f32 "
        "{%0,%1,%2,%3}, {%4,%5,%6,%7}, {%8,%9}, {%0,%1,%2,%3};\n"
        : "+f"(c[0]), "+f"(c[1]), "+f"(c[2]), "+f"(c[3])
        : "r"(a[0]), "r"(a[1]), "r"(a[2]), "r"(a[3]), "r"(b[0]), "r"(b[1]));
}

template<bool TRANS_B, bool BIAS>
__global__ __launch_bounds__(256, 2)
void gemm_tf32(const float* __restrict__ Aall, const float* __restrict__ Ball,
               const float* __restrict__ bias, float* __restrict__ Call,
               int M, int N, int K, size_t strA, size_t strB, size_t strC)
{
    extern __shared__ float sm[];
    const float* A = Aall + (size_t)blockIdx.z * strA;
    const float* B = Ball + (size_t)blockIdx.z * strB;
    float*       C = Call + (size_t)blockIdx.z * strC;

    const int tid  = threadIdx.x;
    const int lane = tid & 31;
    const int w    = tid >> 5;
    const int wm   = w & 1;       // 2 warps in M
    const int wn   = w >> 1;      // 4 warps in N
    const int m0   = blockIdx.y * BM;
    const int n0   = blockIdx.x * BN;

    // smem tile base pointers: [buf][A_hi,A_lo,B_hi,B_lo][TILE_F]
    // index helper done inline via (buf*4 + which)*TILE_F

    // ---- global load addressing ----
    // A tile: 128 rows x 16 k. 2 threads/row, 8 floats each (2 x float4).
    const int arow = tid >> 1;
    const int ak0  = (tid & 1) * 8;
    const float* Aptr = A + (size_t)(m0 + arow) * K + ak0;

    const float* Bptr;
    int brow = 0, bk0 = 0, bkrow = 0, bncol = 0;
    if (TRANS_B) {
        brow = tid >> 1;              // N direction (128 rows)
        bk0  = (tid & 1) * 8;         // K direction
        Bptr = B + (size_t)(n0 + brow) * K + bk0;
    } else {
        bkrow = tid >> 5;             // 0..7 in K (and +8 for second load)
        bncol = (tid & 31) * 4;       // N direction
        Bptr = B + (size_t)bkrow * N + n0 + bncol;
    }

    float acc[4][4][4];
    #pragma unroll
    for (int i = 0; i < 4; i++)
        #pragma unroll
        for (int j = 0; j < 4; j++)
            #pragma unroll
            for (int k = 0; k < 4; k++) acc[i][j][k] = 0.0f;

    const int r = lane >> 2;   // group id (0..7)
    const int c = lane & 3;    // thread-in-group (0..3)

    float4 aR0, aR1, bR0, bR1;

    // ---- prologue: load tile 0 ----
    aR0 = *(const float4*)(Aptr);
    aR1 = *(const float4*)(Aptr + 4);
    if (TRANS_B) {
        bR0 = *(const float4*)(Bptr);
        bR1 = *(const float4*)(Bptr + 4);
    } else {
        bR0 = *(const float4*)(Bptr);
        bR1 = *(const float4*)(Bptr + (size_t)8 * N);
    }

    const int ntiles = K / BK;
    int buf = 0;

    // store helper expressed as a macro-like lambda body (manually inlined)
    // to keep everything in registers.
    {
        float* AH = sm + (0*4 + 0) * TILE_F;
        float* AL = sm + (0*4 + 1) * TILE_F;
        float* BH = sm + (0*4 + 2) * TILE_F;
        float* BL = sm + (0*4 + 3) * TILE_F;
        float va[8] = {aR0.x, aR0.y, aR0.z, aR0.w, aR1.x, aR1.y, aR1.z, aR1.w};
        #pragma unroll
        for (int j = 0; j < 8; j++) {
            float hi, lo; split_tf32(va[j], hi, lo);
            AH[arow * SA + ak0 + j] = hi;
            AL[arow * SA + ak0 + j] = lo;
        }
        if (TRANS_B) {
            float vb[8] = {bR0.x, bR0.y, bR0.z, bR0.w, bR1.x, bR1.y, bR1.z, bR1.w};
            #pragma unroll
            for (int j = 0; j < 8; j++) {
                float hi, lo; split_tf32(vb[j], hi, lo);
                BH[brow * SA + bk0 + j] = hi;
                BL[brow * SA + bk0 + j] = lo;
            }
        } else {
            float v0[4] = {bR0.x, bR0.y, bR0.z, bR0.w};
            float v1[4] = {bR1.x, bR1.y, bR1.z, bR1.w};
            #pragma unroll
            for (int j = 0; j < 4; j++) {
                float hi, lo; split_tf32(v0[j], hi, lo);
                BH[(bncol + j) * SA + bkrow] = hi;
                BL[(bncol + j) * SA + bkrow] = lo;
            }
            #pragma unroll
            for (int j = 0; j < 4; j++) {
                float hi, lo; split_tf32(v1[j], hi, lo);
                BH[(bncol + j) * SA + bkrow + 8] = hi;
                BL[(bncol + j) * SA + bkrow + 8] = lo;
            }
        }
    }
    __syncthreads();

    for (int kt = 0; kt < ntiles; kt++) {
        // prefetch next tile into registers
        if (kt + 1 < ntiles) {
            const float* Ap = Aptr + (size_t)(kt + 1) * BK;
            aR0 = *(const float4*)(Ap);
            aR1 = *(const float4*)(Ap + 4);
            if (TRANS_B) {
                const float* Bpp = Bptr + (size_t)(kt + 1) * BK;
                bR0 = *(const float4*)(Bpp);
                bR1 = *(const float4*)(Bpp + 4);
            } else {
                const float* Bpp = Bptr + (size_t)(kt + 1) * BK * N;
                bR0 = *(const float4*)(Bpp);
                bR1 = *(const float4*)(Bpp + (size_t)8 * N);
            }
        }

        // ---- compute on buffer `buf` ----
        {
            const float* AH = sm + (buf*4 + 0) * TILE_F;
            const float* AL = sm + (buf*4 + 1) * TILE_F;
            const float* BH = sm + (buf*4 + 2) * TILE_F;
            const float* BL = sm + (buf*4 + 3) * TILE_F;

            #pragma unroll
            for (int ks = 0; ks < BK; ks += 8) {
                uint32_t af[4][4], bh[4][2], bl[4][2];

                #pragma unroll
                for (int mi = 0; mi < 4; mi++) {
                    const int rb = wm * 64 + mi * 16;
                    af[mi][0] = f2u(AH[(rb + r    ) * SA + ks + c    ]);
                    af[mi][1] = f2u(AH[(rb + r + 8) * SA + ks + c    ]);
                    af[mi][2] = f2u(AH[(rb + r    ) * SA + ks + c + 4]);
                    af[mi][3] = f2u(AH[(rb + r + 8) * SA + ks + c + 4]);
                }
                #pragma unroll
                for (int ni = 0; ni < 4; ni++) {
                    const int cb = wn * 32 + ni * 8;
                    bh[ni][0] = f2u(BH[(cb + r) * SA + ks + c    ]);
                    bh[ni][1] = f2u(BH[(cb + r) * SA + ks + c + 4]);
                    bl[ni][0] = f2u(BL[(cb + r) * SA + ks + c    ]);
                    bl[ni][1] = f2u(BL[(cb + r) * SA + ks + c + 4]);
                }

                // term 1: a_hi * b_hi
                #pragma unroll
                for (int mi = 0; mi < 4; mi++)
                    #pragma unroll
                    for (int ni = 0; ni < 4; ni++)
                        mma8(acc[mi][ni], af[mi], bh[ni]);

                // term 2: a_hi * b_lo
                #pragma unroll
                for (int mi = 0; mi < 4; mi++)
                    #pragma unroll
                    for (int ni = 0; ni < 4; ni++)
                        mma8(acc[mi][ni], af[mi], bl[ni]);

                // reload A fragments with lo part
                #pragma unroll
                for (int mi = 0; mi < 4; mi++) {
                    const int rb = wm * 64 + mi * 16;
                    af[mi][0] = f2u(AL[(rb + r    ) * SA + ks + c    ]);
                    af[mi][1] = f2u(AL[(rb + r + 8) * SA + ks + c    ]);
                    af[mi][2] = f2u(AL[(rb + r    ) * SA + ks + c + 4]);
                    af[mi][3] = f2u(AL[(rb + r + 8) * SA + ks + c + 4]);
                }

                // term 3: a_lo * b_hi
                #pragma unroll
                for (int mi = 0; mi < 4; mi++)
                    #pragma unroll
                    for (int ni = 0; ni < 4; ni++)
                        mma8(acc[mi][ni], af[mi], bh[ni]);
            }
        }

        // ---- store prefetched tile into other buffer ----
        if (kt + 1 < ntiles) {
            buf ^= 1;
            float* AH = sm + (buf*4 + 0) * TILE_F;
            float* AL = sm + (buf*4 + 1) * TILE_F;
            float* BH = sm + (buf*4 + 2) * TILE_F;
            float* BL = sm + (buf*4 + 3) * TILE_F;
            float va[8] = {aR0.x, aR0.y, aR0.z, aR0.w, aR1.x, aR1.y, aR1.z, aR1.w};
            #pragma unroll
            for (int j = 0; j < 8; j++) {
                float hi, lo; split_tf32(va[j], hi, lo);
                AH[arow * SA + ak0 + j] = hi;
                AL[arow * SA + ak0 + j] = lo;
            }
            if (TRANS_B) {
                float vb[8] = {bR0.x, bR0.y, bR0.z, bR0.w, bR1.x, bR1.y, bR1.z, bR1.w};
                #pragma unroll
                for (int j = 0; j < 8; j++) {
                    float hi, lo; split_tf32(vb[j], hi, lo);
                    BH[brow * SA + bk0 + j] = hi;
                    BL[brow * SA + bk0 + j] = lo;
                }
            } else {
                float v0[4] = {bR0.x, bR0.y, bR0.z, bR0.w};
                float v1[4] = {bR1.x, bR1.y, bR1.z, bR1.w};
                #pragma unroll
                for (int j = 0; j < 4; j++) {
                    float hi, lo; split_tf32(v0[j], hi, lo);
                    BH[(bncol + j) * SA + bkrow] = hi;
                    BL[(bncol + j) * SA + bkrow] = lo;
                }
                #pragma unroll
                for (int j = 0; j < 4; j++) {
                    float hi, lo; split_tf32(v1[j], hi, lo);
                    BH[(bncol + j) * SA + bkrow + 8] = hi;
                    BL[(bncol + j) * SA + bkrow + 8] = lo;
                }
            }
            __syncthreads();
        }
    }

    // ---- epilogue: write C (+bias) ----
    #pragma unroll
    for (int mi = 0; mi < 4; mi++) {
        #pragma unroll
        for (int ni = 0; ni < 4; ni++) {
            const int row = m0 + wm * 64 + mi * 16 + r;
            const int col = n0 + wn * 32 + ni * 8 + c * 2;
            float2 v0 = make_float2(acc[mi][ni][0], acc[mi][ni][1]);
            float2 v1 = make_float2(acc[mi][ni][2], acc[mi][ni][3]);
            if (BIAS) {
                float2 bb = *(const float2*)&bias[col];
                v0.x += bb.x; v0.y += bb.y;
                v1.x += bb.x; v1.y += bb.y;
            }
            *(float2*)&C[(size_t)row * N + col]       = v0;
            *(float2*)&C[(size_t)(row + 8) * N + col] = v1;
        }
    }
}

// ---------------------------------------------------------------------------
// Row softmax over rows of length SEQ=2048. One 256-thread block per row,
// 8 elements per thread in registers. Max-subtraction mandatory
// (unscaled logits, std ~22).
// ---------------------------------------------------------------------------
__global__ __launch_bounds__(256)
void softmax2048(float* __restrict__ S)
{
    __shared__ float sh[8];
    float* p = S + (size_t)blockIdx.x * SEQ;
    const int tid  = threadIdx.x;
    const int lane = tid & 31;
    const int wid  = tid >> 5;

    float4 v0 = ((const float4*)p)[tid];
    float4 v1 = ((const float4*)p)[tid + 256];

    float m = fmaxf(fmaxf(fmaxf(v0.x, v0.y), fmaxf(v0.z, v0.w)),
                    fmaxf(fmaxf(v1.x, v1.y), fmaxf(v1.z, v1.w)));
    #pragma unroll
    for (int o = 16; o > 0; o >>= 1)
        m = fmaxf(m, __shfl_xor_sync(0xffffffffu, m, o));
    if (lane == 0) sh[wid] = m;
    __syncthreads();
    m = sh[0];
    #pragma unroll
    for (int i = 1; i < 8; i++) m = fmaxf(m, sh[i]);
    __syncthreads();

    v0.x = expf(v0.x - m); v0.y = expf(v0.y - m);
    v0.z = expf(v0.z - m); v0.w = expf(v0.w - m);
    v1.x = expf(v1.x - m); v1.y = expf(v1.y - m);
    v1.z = expf(v1.z - m); v1.w = expf(v1.w - m);

    float s = v0.x + v0.y + v0.z + v0.w + v1.x + v1.y + v1.z + v1.w;
    #pragma unroll
    for (int o = 16; o > 0; o >>= 1)
        s += __shfl_xor_sync(0xffffffffu, s, o);
    if (lane == 0) sh[wid] = s;
    __syncthreads();
    s = sh[0] + sh[1] + sh[2] + sh[3] + sh[4] + sh[5] + sh[6] + sh[7];

    const float inv = 1.0f / s;
    v0.x *= inv; v0.y *= inv; v0.z *= inv; v0.w *= inv;
    v1.x *= inv; v1.y *= inv; v1.z *= inv; v1.w *= inv;

    ((float4*)p)[tid]       = v0;
    ((float4*)p)[tid + 256] = v1;
}

extern "C" void kernel_launch(void* const* d_in, const int* in_sizes, int n_in,
                              void* d_out, int out_size)
{
    const float* x  = (const float*)d_in[0];
    const float* Wq = (const float*)d_in[1];
    const float* bq = (const float*)d_in[2];
    const float* Wk = (const float*)d_in[3];
    const float* bk = (const float*)d_in[4];
    const float* Wv = (const float*)d_in[5];
    const float* bv = (const float*)d_in[6];
    float* out = (float*)d_out;

    float *Q, *K, *V, *S;
    cudaGetSymbolAddress((void**)&Q, g_Q);
    cudaGetSymbolAddress((void**)&K, g_K);
    cudaGetSymbolAddress((void**)&V, g_V);
    cudaGetSymbolAddress((void**)&S, g_S);

    // opt-in to >48KB dynamic smem (idempotent; host-side, capture-safe)
    cudaFuncSetAttribute(gemm_tf32<true,  true >, cudaFuncAttributeMaxDynamicSharedMemorySize, SMEM_BYTES);
    cudaFuncSetAttribute(gemm_tf32<true,  false>, cudaFuncAttributeMaxDynamicSharedMemorySize, SMEM_BYTES);
    cudaFuncSetAttribute(gemm_tf32<false, false>, cudaFuncAttributeMaxDynamicSharedMemorySize, SMEM_BYTES);

    const dim3 t(256);

    // QKV projections: C[16384,512] = x * W^T + b
    const dim3 gq(DIM / 128, MQKV / 128, 1);
    gemm_tf32<true,  true ><<<gq, t, SMEM_BYTES>>>(x, Wq, bq, Q, MQKV, DIM, DIM, 0, 0, 0);
    gemm_tf32<true,  true ><<<gq, t, SMEM_BYTES>>>(x, Wk, bk, K, MQKV, DIM, DIM, 0, 0, 0);
    gemm_tf32<true,  true ><<<gq, t, SMEM_BYTES>>>(x, Wv, bv, V, MQKV, DIM, DIM, 0, 0, 0);

    // S[b] = Q[b] * K[b]^T : [2048,2048] x 8
    const dim3 gs(SEQ / 128, SEQ / 128, BATCH);
    gemm_tf32<true,  false><<<gs, t, SMEM_BYTES>>>(Q, K, nullptr, S, SEQ, SEQ, DIM,
                                                   (size_t)SEQ * DIM, (size_t)SEQ * DIM,
                                                   (size_t)SEQ * SEQ);

    // row softmax over keys
    softmax2048<<<BATCH * SEQ, 256>>>(S);

    // O[b] = P[b] * V[b] : [2048,512] x 8
    const dim3 go(DIM / 128, SEQ / 128, BATCH);
    gemm_tf32<false, false><<<go, t, SMEM_BYTES>>>(S, V, nullptr, out, SEQ, DIM, SEQ,
                                                   (size_t)SEQ * SEQ, (size_t)SEQ * DIM,
                                                   (size_t)SEQ * DIM);
}

// round 3
// speedup vs baseline: 1.9498x; 1.9498x over previous
#include <cuda_runtime.h>
#include <cuda_bf16.h>
#include <cstdint>

// Problem shape (fixed by the reference)
#define BATCH 8
#define SEQ   2048
#define DIM   512
#define MQKV  (BATCH*SEQ)   // 16384

// Scratch (device globals: allocation-free per harness rules)
__device__ float g_Q[BATCH*SEQ*DIM];                 // 32 MB
__device__ float g_K[BATCH*SEQ*DIM];                 // 32 MB
__device__ float g_V[BATCH*SEQ*DIM];                 // 32 MB
__device__ float g_S[(size_t)BATCH*SEQ*SEQ];         // 128 MB

// ---------------------------------------------------------------------------
// bf16 3-term error-compensated tensor-core GEMM.
// x = hi + lo (bf16 each); x*y ~= xh*yh + xh*yl + xl*yh  (drop lo*lo, ~2^-18)
// Tile 128x128x16(f32 k), 256 threads = 8 warps (2x4), warp tile 64x32,
// mma.sync.m16n8k16.bf16, fp32 accumulate. Double-buffered smem.
// Smem holds packed bf16x2 words: [row][kpair], row stride 12 words
// (12r+c mod 32 hits all 32 banks -> conflict-free scalar fragment loads).
//   TRANS_B = true : B is [N,K] row-major (C = A * B^T)
//   TRANS_B = false: B is [K,N] row-major (C = A * B); packed vertically,
//                    with an XOR column swizzle to avoid store conflicts.
// ---------------------------------------------------------------------------
#define ASTRW 12                 // words per smem row
#define TILEW (128*ASTRW)        // words per [128-row] tile plane

__device__ __forceinline__ uint32_t b2u(__nv_bfloat162 h)
{
    return *reinterpret_cast<uint32_t*>(&h);
}

// Split a pair of fp32 (consecutive k) into packed bf16x2 hi and lo words.
__device__ __forceinline__ void split2(float x0, float x1, uint32_t& hi, uint32_t& lo)
{
    __nv_bfloat162 h = __floats2bfloat162_rn(x0, x1);   // .x = x0 (low half)
    float r0 = x0 - __bfloat162float(__low2bfloat16(h));
    float r1 = x1 - __bfloat162float(__high2bfloat16(h));
    hi = b2u(h);
    lo = b2u(__floats2bfloat162_rn(r0, r1));
}

// Split 8 consecutive k-values (two float4) into 4 hi + 4 lo packed words.
__device__ __forceinline__ void split8(const float4& v0, const float4& v1,
                                       uint32_t hi[4], uint32_t lo[4])
{
    split2(v0.x, v0.y, hi[0], lo[0]);
    split2(v0.z, v0.w, hi[1], lo[1]);
    split2(v1.x, v1.y, hi[2], lo[2]);
    split2(v1.z, v1.w, hi[3], lo[3]);
}

__device__ __forceinline__ void mma16(float* c, const uint32_t* a, const uint32_t* b)
{
    asm volatile(
        "mma.sync.aligned.m16n8k16.row.col.f32.bf16.bf16.f32 "
        "{%0,%1,%2,%3}, {%4,%5,%6,%7}, {%8,%9}, {%0,%1,%2,%3};\n"
        : "+f"(c[0]), "+f"(c[1]), "+f"(c[2]), "+f"(c[3])
        : "r"(a[0]), "r"(a[1]), "r"(a[2]), "r"(a[3]), "r"(b[0]), "r"(b[1]));
}

template<bool TRANS_B, bool BIAS>
__global__ __launch_bounds__(256, 2)
void gemm_bf16c(const float* __restrict__ Aall, const float* __restrict__ Ball,
                const float* __restrict__ bias, float* __restrict__ Call,
                int M, int N, int K, size_t strA, size_t strB, size_t strC)
{
    __shared__ __align__(16) uint32_t smA[2][2][TILEW];  // [buf][hi/lo]
    __shared__ __align__(16) uint32_t smB[2][2][TILEW];

    const float* A = Aall + (size_t)blockIdx.z * strA;
    const float* B = Ball + (size_t)blockIdx.z * strB;
    float*       C = Call + (size_t)blockIdx.z * strC;

    const int tid  = threadIdx.x;
    const int lane = tid & 31;
    const int w    = tid >> 5;
    const int wm   = w & 1;        // 2 warps in M
    const int wn   = w >> 1;       // 4 warps in N
    const int m0   = blockIdx.y * 128;
    const int n0   = blockIdx.x * 128;

    // ---- global load addressing ----
    // A tile: 128 rows x 16 k. 2 threads/row, 8 floats (2 x float4) each.
    const int arow  = tid >> 1;
    const int ak0   = (tid & 1) * 8;
    const int awoff = arow * ASTRW + (tid & 1) * 4;   // word offset (16B-aligned)
    const float* Aptr = A + (size_t)(m0 + arow) * K + ak0;

    const float* Bptr = nullptr;
    int bwoff = 0;                  // TRANS_B store offset
    int kp = 0, nc = 0, bxor = 0;   // !TRANS_B store params
    if (TRANS_B) {
        const int brow = tid >> 1;
        bwoff = brow * ASTRW + (tid & 1) * 4;
        Bptr  = B + (size_t)(n0 + brow) * K + (tid & 1) * 8;
    } else {
        kp   = tid >> 5;            // k-pair index 0..7 (rows 2kp, 2kp+1)
        nc   = (tid & 31) * 4;      // 4 consecutive n
        bxor = (nc >> 2) & 7;       // column swizzle (fn of row only)
        Bptr = B + (size_t)(2 * kp) * N + n0 + nc;
    }

    float acc[4][4][4];
    #pragma unroll
    for (int i = 0; i < 4; i++)
        #pragma unroll
        for (int j = 0; j < 4; j++)
            #pragma unroll
            for (int k = 0; k < 4; k++) acc[i][j][k] = 0.0f;

    const int r = lane >> 2;   // 0..7
    const int c = lane & 3;    // 0..3

    float4 aR0, aR1, bR0, bR1;

    // ---- prologue: load + split + store tile 0 ----
    aR0 = *(const float4*)(Aptr);
    aR1 = *(const float4*)(Aptr + 4);
    if (TRANS_B) {
        bR0 = *(const float4*)(Bptr);
        bR1 = *(const float4*)(Bptr + 4);
    } else {
        bR0 = *(const float4*)(Bptr);             // row 2kp
        bR1 = *(const float4*)(Bptr + N);         // row 2kp+1
    }
    {
        uint32_t hi[4], lo[4];
        split8(aR0, aR1, hi, lo);
        *(uint4*)&smA[0][0][awoff] = make_uint4(hi[0], hi[1], hi[2], hi[3]);
        *(uint4*)&smA[0][1][awoff] = make_uint4(lo[0], lo[1], lo[2], lo[3]);
        if (TRANS_B) {
            split8(bR0, bR1, hi, lo);
            *(uint4*)&smB[0][0][bwoff] = make_uint4(hi[0], hi[1], hi[2], hi[3]);
            *(uint4*)&smB[0][1][bwoff] = make_uint4(lo[0], lo[1], lo[2], lo[3]);
        } else {
            float t0[4] = {bR0.x, bR0.y, bR0.z, bR0.w};
            float t1[4] = {bR1.x, bR1.y, bR1.z, bR1.w};
            #pragma unroll
            for (int i = 0; i < 4; i++) {
                uint32_t h, l;
                split2(t0[i], t1[i], h, l);      // low = k even (row 2kp)
                smB[0][0][(nc + i) * ASTRW + (kp ^ bxor)] = h;
                smB[0][1][(nc + i) * ASTRW + (kp ^ bxor)] = l;
            }
        }
    }
    __syncthreads();

    const int ntiles = K >> 4;
    int buf = 0;

    for (int kt = 0; kt < ntiles; kt++) {
        // prefetch next tile into registers
        if (kt + 1 < ntiles) {
            const float* Ap = Aptr + (size_t)(kt + 1) * 16;
            aR0 = *(const float4*)(Ap);
            aR1 = *(const float4*)(Ap + 4);
            if (TRANS_B) {
                const float* Bp = Bptr + (size_t)(kt + 1) * 16;
                bR0 = *(const float4*)(Bp);
                bR1 = *(const float4*)(Bp + 4);
            } else {
                const float* Bp = Bptr + (size_t)(kt + 1) * 16 * N;
                bR0 = *(const float4*)(Bp);
                bR1 = *(const float4*)(Bp + N);
            }
        }

        // ---- compute on buffer `buf` (one k16 MMA step) ----
        {
            const uint32_t* AH = smA[buf][0];
            const uint32_t* AL = smA[buf][1];
            const uint32_t* BH = smB[buf][0];
            const uint32_t* BL = smB[buf][1];

            uint32_t bh[4][2], bl[4][2];
            #pragma unroll
            for (int ni = 0; ni < 4; ni++) {
                const int row = wn * 32 + ni * 8 + r;
                const int c0 = TRANS_B ? c       : (c ^ ((row >> 2) & 7));
                const int c1 = TRANS_B ? (c + 4) : ((c + 4) ^ ((row >> 2) & 7));
                bh[ni][0] = BH[row * ASTRW + c0];
                bh[ni][1] = BH[row * ASTRW + c1];
                bl[ni][0] = BL[row * ASTRW + c0];
                bl[ni][1] = BL[row * ASTRW + c1];
            }

            uint32_t af[4][4];
            #pragma unroll
            for (int mi = 0; mi < 4; mi++) {
                const int rb = wm * 64 + mi * 16;
                af[mi][0] = AH[(rb + r    ) * ASTRW + c    ];
                af[mi][1] = AH[(rb + r + 8) * ASTRW + c    ];
                af[mi][2] = AH[(rb + r    ) * ASTRW + c + 4];
                af[mi][3] = AH[(rb + r + 8) * ASTRW + c + 4];
            }

            // term 1: a_hi * b_hi
            #pragma unroll
            for (int mi = 0; mi < 4; mi++)
                #pragma unroll
                for (int ni = 0; ni < 4; ni++)
                    mma16(acc[mi][ni], af[mi], bh[ni]);
            // term 2: a_hi * b_lo
            #pragma unroll
            for (int mi = 0; mi < 4; mi++)
                #pragma unroll
                for (int ni = 0; ni < 4; ni++)
                    mma16(acc[mi][ni], af[mi], bl[ni]);

            // reload A with lo parts
            #pragma unroll
            for (int mi = 0; mi < 4; mi++) {
                const int rb = wm * 64 + mi * 16;
                af[mi][0] = AL[(rb + r    ) * ASTRW + c    ];
                af[mi][1] = AL[(rb + r + 8) * ASTRW + c    ];
                af[mi][2] = AL[(rb + r    ) * ASTRW + c + 4];
                af[mi][3] = AL[(rb + r + 8) * ASTRW + c + 4];
            }
            // term 3: a_lo * b_hi
            #pragma unroll
            for (int mi = 0; mi < 4; mi++)
                #pragma unroll
                for (int ni = 0; ni < 4; ni++)
                    mma16(acc[mi][ni], af[mi], bh[ni]);
        }

        // ---- store prefetched tile into other buffer ----
        if (kt + 1 < ntiles) {
            buf ^= 1;
            uint32_t hi[4], lo[4];
            split8(aR0, aR1, hi, lo);
            *(uint4*)&smA[buf][0][awoff] = make_uint4(hi[0], hi[1], hi[2], hi[3]);
            *(uint4*)&smA[buf][1][awoff] = make_uint4(lo[0], lo[1], lo[2], lo[3]);
            if (TRANS_B) {
                split8(bR0, bR1, hi, lo);
                *(uint4*)&smB[buf][0][bwoff] = make_uint4(hi[0], hi[1], hi[2], hi[3]);
                *(uint4*)&smB[buf][1][bwoff] = make_uint4(lo[0], lo[1], lo[2], lo[3]);
            } else {
                float t0[4] = {bR0.x, bR0.y, bR0.z, bR0.w};
                float t1[4] = {bR1.x, bR1.y, bR1.z, bR1.w};
                #pragma unroll
                for (int i = 0; i < 4; i++) {
                    uint32_t h, l;
                    split2(t0[i], t1[i], h, l);
                    smB[buf][0][(nc + i) * ASTRW + (kp ^ bxor)] = h;
                    smB[buf][1][(nc + i) * ASTRW + (kp ^ bxor)] = l;
                }
            }
            __syncthreads();
        }
    }

    // ---- epilogue: write C (+bias). c0,c1=(r, 2c..2c+1); c2,c3=(r+8, ..) ----
    #pragma unroll
    for (int mi = 0; mi < 4; mi++) {
        #pragma unroll
        for (int ni = 0; ni < 4; ni++) {
            const int row = m0 + wm * 64 + mi * 16 + r;
            const int col = n0 + wn * 32 + ni * 8 + c * 2;
            float2 v0 = make_float2(acc[mi][ni][0], acc[mi][ni][1]);
            float2 v1 = make_float2(acc[mi][ni][2], acc[mi][ni][3]);
            if (BIAS) {
                float2 bb = *(const float2*)&bias[col];
                v0.x += bb.x; v0.y += bb.y;
                v1.x += bb.x; v1.y += bb.y;
            }
            *(float2*)&C[(size_t)row * N + col]       = v0;
            *(float2*)&C[(size_t)(row + 8) * N + col] = v1;
        }
    }
}

// ---------------------------------------------------------------------------
// Row softmax over rows of length SEQ=2048. One 256-thread block per row,
// 8 elements per thread in registers. Max-subtraction mandatory
// (unscaled logits, std ~22).
// ---------------------------------------------------------------------------
__global__ __launch_bounds__(256)
void softmax2048(float* __restrict__ S)
{
    __shared__ float sh[8];
    float* p = S + (size_t)blockIdx.x * SEQ;
    const int tid  = threadIdx.x;
    const int lane = tid & 31;
    const int wid  = tid >> 5;

    float4 v0 = ((const float4*)p)[tid];
    float4 v1 = ((const float4*)p)[tid + 256];

    float m = fmaxf(fmaxf(fmaxf(v0.x, v0.y), fmaxf(v0.z, v0.w)),
                    fmaxf(fmaxf(v1.x, v1.y), fmaxf(v1.z, v1.w)));
    #pragma unroll
    for (int o = 16; o > 0; o >>= 1)
        m = fmaxf(m, __shfl_xor_sync(0xffffffffu, m, o));
    if (lane == 0) sh[wid] = m;
    __syncthreads();
    m = sh[0];
    #pragma unroll
    for (int i = 1; i < 8; i++) m = fmaxf(m, sh[i]);
    __syncthreads();

    v0.x = expf(v0.x - m); v0.y = expf(v0.y - m);
    v0.z = expf(v0.z - m); v0.w = expf(v0.w - m);
    v1.x = expf(v1.x - m); v1.y = expf(v1.y - m);
    v1.z = expf(v1.z - m); v1.w = expf(v1.w - m);

    float s = v0.x + v0.y + v0.z + v0.w + v1.x + v1.y + v1.z + v1.w;
    #pragma unroll
    for (int o = 16; o > 0; o >>= 1)
        s += __shfl_xor_sync(0xffffffffu, s, o);
    if (lane == 0) sh[wid] = s;
    __syncthreads();
    s = sh[0] + sh[1] + sh[2] + sh[3] + sh[4] + sh[5] + sh[6] + sh[7];

    const float inv = 1.0f / s;
    v0.x *= inv; v0.y *= inv; v0.z *= inv; v0.w *= inv;
    v1.x *= inv; v1.y *= inv; v1.z *= inv; v1.w *= inv;

    ((float4*)p)[tid]       = v0;
    ((float4*)p)[tid + 256] = v1;
}

extern "C" void kernel_launch(void* const* d_in, const int* in_sizes, int n_in,
                              void* d_out, int out_size)
{
    const float* x  = (const float*)d_in[0];
    const float* Wq = (const float*)d_in[1];
    const float* bq = (const float*)d_in[2];
    const float* Wk = (const float*)d_in[3];
    const float* bk = (const float*)d_in[4];
    const float* Wv = (const float*)d_in[5];
    const float* bv = (const float*)d_in[6];
    float* out = (float*)d_out;

    float *Q, *K, *V, *S;
    cudaGetSymbolAddress((void**)&Q, g_Q);
    cudaGetSymbolAddress((void**)&K, g_K);
    cudaGetSymbolAddress((void**)&V, g_V);
    cudaGetSymbolAddress((void**)&S, g_S);

    const dim3 t(256);

    // QKV projections: C[16384,512] = x * W^T + b
    const dim3 gq(DIM / 128, MQKV / 128, 1);
    gemm_bf16c<true,  true ><<<gq, t>>>(x, Wq, bq, Q, MQKV, DIM, DIM, 0, 0, 0);
    gemm_bf16c<true,  true ><<<gq, t>>>(x, Wk, bk, K, MQKV, DIM, DIM, 0, 0, 0);
    gemm_bf16c<true,  true ><<<gq, t>>>(x, Wv, bv, V, MQKV, DIM, DIM, 0, 0, 0);

    // S[b] = Q[b] * K[b]^T : [2048,2048] x 8
    const dim3 gs(SEQ / 128, SEQ / 128, BATCH);
    gemm_bf16c<true,  false><<<gs, t>>>(Q, K, nullptr, S, SEQ, SEQ, DIM,
                                        (size_t)SEQ * DIM, (size_t)SEQ * DIM,
                                        (size_t)SEQ * SEQ);

    // row softmax over keys
    softmax2048<<<BATCH * SEQ, 256>>>(S);

    // O[b] = P[b] * V[b] : [2048,512] x 8
    const dim3 go(DIM / 128, SEQ / 128, BATCH);
    gemm_bf16c<false, false><<<go, t>>>(S, V, nullptr, out, SEQ, DIM, SEQ,
                                        (size_t)SEQ * SEQ, (size_t)SEQ * DIM,
                                        (size_t)SEQ * DIM);
}

// round 4
// speedup vs baseline: 2.2274x; 1.1424x over previous
#include <cuda_runtime.h>
#include <cuda_bf16.h>
#include <cstdint>

// Problem shape (fixed by the reference)
#define BATCH 8
#define SEQ   2048
#define DIM   512
#define MQKV  (BATCH*SEQ)   // 16384

// Scratch (device globals: allocation-free per harness rules)
__device__ float g_Q[BATCH*SEQ*DIM];                 // 32 MB
__device__ float g_K[BATCH*SEQ*DIM];                 // 32 MB
__device__ float g_V[BATCH*SEQ*DIM];                 // 32 MB
__device__ float g_Vt[BATCH*SEQ*DIM];                // 32 MB (V transposed per batch)
__device__ float g_S[(size_t)BATCH*SEQ*SEQ];         // 128 MB

// ---------------------------------------------------------------------------
// bf16 3-term error-compensated tensor-core GEMM (C = A * B^T [+bias]).
// x = hi + lo (bf16 each); x*y ~= xh*yh + xh*yl + xl*yh  (drop lo*lo, ~2^-18)
// Tile 128x128x16, 256 threads = 8 warps (2x4), warp tile 64x32,
// mma.sync.m16n8k16.bf16 fp32-accum, double-buffered smem, fragment loads
// via ldmatrix.x4 (12 LDSM per warp per k-step instead of 48 scalar LDS).
// Smem: packed bf16x2 words, [row][kpair], row stride 12 words
// (12r+c mod 32 covers all banks -> conflict-free LDSM phases).
// A is [M,K] row-major; B is [N,K] row-major (both K-contiguous).
// ---------------------------------------------------------------------------
#define ASTRW 12                 // words per smem row
#define TILEW (128*ASTRW)        // words per [128-row] tile plane
#define PLANEB (TILEW*4)         // plane stride in bytes
#define BUFB   (2*PLANEB)        // buffer stride in bytes (hi+lo planes)

__device__ __forceinline__ uint32_t b2u(__nv_bfloat162 h)
{
    return *reinterpret_cast<uint32_t*>(&h);
}

// Split a pair of fp32 (consecutive k) into packed bf16x2 hi and lo words.
__device__ __forceinline__ void split2(float x0, float x1, uint32_t& hi, uint32_t& lo)
{
    __nv_bfloat162 h = __floats2bfloat162_rn(x0, x1);   // .x = x0 (low half)
    float r0 = x0 - __bfloat162float(__low2bfloat16(h));
    float r1 = x1 - __bfloat162float(__high2bfloat16(h));
    hi = b2u(h);
    lo = b2u(__floats2bfloat162_rn(r0, r1));
}

__device__ __forceinline__ void split8(const float4& v0, const float4& v1,
                                       uint32_t hi[4], uint32_t lo[4])
{
    split2(v0.x, v0.y, hi[0], lo[0]);
    split2(v0.z, v0.w, hi[1], lo[1]);
    split2(v1.x, v1.y, hi[2], lo[2]);
    split2(v1.z, v1.w, hi[3], lo[3]);
}

__device__ __forceinline__ void mma16(float* c, const uint32_t* a, const uint32_t* b)
{
    asm volatile(
        "mma.sync.aligned.m16n8k16.row.col.f32.bf16.bf16.f32 "
        "{%0,%1,%2,%3}, {%4,%5,%6,%7}, {%8,%9}, {%0,%1,%2,%3};\n"
        : "+f"(c[0]), "+f"(c[1]), "+f"(c[2]), "+f"(c[3])
        : "r"(a[0]), "r"(a[1]), "r"(a[2]), "r"(a[3]), "r"(b[0]), "r"(b[1]));
}

__device__ __forceinline__ void ldsm_x4(uint32_t& r0, uint32_t& r1,
                                        uint32_t& r2, uint32_t& r3, uint32_t addr)
{
    asm volatile("ldmatrix.sync.aligned.m8n8.x4.shared.b16 {%0,%1,%2,%3}, [%4];"
                 : "=r"(r0), "=r"(r1), "=r"(r2), "=r"(r3) : "r"(addr));
}

template<bool BIAS>
__global__ __launch_bounds__(256, 2)
void gemm_bf16c(const float* __restrict__ Aall, const float* __restrict__ Ball,
                const float* __restrict__ bias, float* __restrict__ Call,
                int M, int N, int K, size_t strA, size_t strB, size_t strC)
{
    __shared__ __align__(16) uint32_t smA[2][2][TILEW];  // [buf][hi/lo]
    __shared__ __align__(16) uint32_t smB[2][2][TILEW];

    const float* A = Aall + (size_t)blockIdx.z * strA;
    const float* B = Ball + (size_t)blockIdx.z * strB;
    float*       C = Call + (size_t)blockIdx.z * strC;

    const int tid  = threadIdx.x;
    const int lane = tid & 31;
    const int w    = tid >> 5;
    const int wm   = w & 1;        // 2 warps in M
    const int wn   = w >> 1;       // 4 warps in N
    const int m0   = blockIdx.y * 128;
    const int n0   = blockIdx.x * 128;

    // ---- global load addressing: 128 rows x 16 k, 2 threads/row ----
    const int grow  = tid >> 1;
    const int gk0   = (tid & 1) * 8;
    const int woff  = grow * ASTRW + (tid & 1) * 4;   // 16B-aligned word offset
    const float* Aptr = A + (size_t)(m0 + grow) * K + gk0;
    const float* Bptr = B + (size_t)(n0 + grow) * K + gk0;

    // ---- ldmatrix per-lane addresses (word units within a plane) ----
    // A fragment (m16k16): mats = {r0..7 k0..7},{r8..15 k0..7},{r0..7 k8..15},{r8..15 k8..15}
    const int a_r = ((lane >> 3) & 1) * 8 + (lane & 7);
    const int a_c = ((lane >> 4) & 1) * 4;
    // B pair (two 8x16 n-major tiles): mats = {n0..7 k0..7},{n0..7 k8..15},{n8..15 k0..7},{n8..15 k8..15}
    const int b_r = (lane & 7) + ((lane >> 4) & 1) * 8;
    const int b_c = ((lane >> 3) & 1) * 4;

    const uint32_t smA0 = (uint32_t)__cvta_generic_to_shared(&smA[0][0][0]);
    const uint32_t smB0 = (uint32_t)__cvta_generic_to_shared(&smB[0][0][0]);
    const uint32_t aAddr0 = smA0 + (uint32_t)(((wm * 64 + a_r) * ASTRW + a_c) * 4);
    const uint32_t bAddr0 = smB0 + (uint32_t)(((wn * 32 + b_r) * ASTRW + b_c) * 4);

    float acc[4][4][4];
    #pragma unroll
    for (int i = 0; i < 4; i++)
        #pragma unroll
        for (int j = 0; j < 4; j++)
            #pragma unroll
            for (int k = 0; k < 4; k++) acc[i][j][k] = 0.0f;

    const int r = lane >> 2;   // 0..7 (epilogue row)
    const int c = lane & 3;    // 0..3 (epilogue col pair)

    float4 aR0, aR1, bR0, bR1;

    // ---- prologue: load + split + store tile 0 ----
    aR0 = *(const float4*)(Aptr);
    aR1 = *(const float4*)(Aptr + 4);
    bR0 = *(const float4*)(Bptr);
    bR1 = *(const float4*)(Bptr + 4);
    {
        uint32_t hi[4], lo[4];
        split8(aR0, aR1, hi, lo);
        *(uint4*)&smA[0][0][woff] = make_uint4(hi[0], hi[1], hi[2], hi[3]);
        *(uint4*)&smA[0][1][woff] = make_uint4(lo[0], lo[1], lo[2], lo[3]);
        split8(bR0, bR1, hi, lo);
        *(uint4*)&smB[0][0][woff] = make_uint4(hi[0], hi[1], hi[2], hi[3]);
        *(uint4*)&smB[0][1][woff] = make_uint4(lo[0], lo[1], lo[2], lo[3]);
    }
    __syncthreads();

    const int ntiles = K >> 4;
    int buf = 0;

    for (int kt = 0; kt < ntiles; kt++) {
        // prefetch next tile into registers
        if (kt + 1 < ntiles) {
            const float* Ap = Aptr + (size_t)(kt + 1) * 16;
            aR0 = *(const float4*)(Ap);
            aR1 = *(const float4*)(Ap + 4);
            const float* Bp = Bptr + (size_t)(kt + 1) * 16;
            bR0 = *(const float4*)(Bp);
            bR1 = *(const float4*)(Bp + 4);
        }

        // ---- compute on buffer `buf` (one k16 MMA step) ----
        {
            const uint32_t aHi = aAddr0 + (uint32_t)buf * BUFB;
            const uint32_t aLo = aHi + PLANEB;
            const uint32_t bHi = bAddr0 + (uint32_t)buf * BUFB;
            const uint32_t bLo = bHi + PLANEB;

            uint32_t af[4][4], bh[4][2], bl[4][2];
            #pragma unroll
            for (int j = 0; j < 2; j++) {
                ldsm_x4(bh[2*j][0], bh[2*j][1], bh[2*j+1][0], bh[2*j+1][1],
                        bHi + (uint32_t)(j * 16 * ASTRW * 4));
                ldsm_x4(bl[2*j][0], bl[2*j][1], bl[2*j+1][0], bl[2*j+1][1],
                        bLo + (uint32_t)(j * 16 * ASTRW * 4));
            }
            #pragma unroll
            for (int mi = 0; mi < 4; mi++)
                ldsm_x4(af[mi][0], af[mi][1], af[mi][2], af[mi][3],
                        aHi + (uint32_t)(mi * 16 * ASTRW * 4));

            // term 1: a_hi * b_hi
            #pragma unroll
            for (int mi = 0; mi < 4; mi++)
                #pragma unroll
                for (int ni = 0; ni < 4; ni++)
                    mma16(acc[mi][ni], af[mi], bh[ni]);
            // term 2: a_hi * b_lo
            #pragma unroll
            for (int mi = 0; mi < 4; mi++)
                #pragma unroll
                for (int ni = 0; ni < 4; ni++)
                    mma16(acc[mi][ni], af[mi], bl[ni]);

            // reload A with lo parts
            #pragma unroll
            for (int mi = 0; mi < 4; mi++)
                ldsm_x4(af[mi][0], af[mi][1], af[mi][2], af[mi][3],
                        aLo + (uint32_t)(mi * 16 * ASTRW * 4));

            // term 3: a_lo * b_hi
            #pragma unroll
            for (int mi = 0; mi < 4; mi++)
                #pragma unroll
                for (int ni = 0; ni < 4; ni++)
                    mma16(acc[mi][ni], af[mi], bh[ni]);
        }

        // ---- store prefetched tile into other buffer ----
        if (kt + 1 < ntiles) {
            buf ^= 1;
            uint32_t hi[4], lo[4];
            split8(aR0, aR1, hi, lo);
            *(uint4*)&smA[buf][0][woff] = make_uint4(hi[0], hi[1], hi[2], hi[3]);
            *(uint4*)&smA[buf][1][woff] = make_uint4(lo[0], lo[1], lo[2], lo[3]);
            split8(bR0, bR1, hi, lo);
            *(uint4*)&smB[buf][0][woff] = make_uint4(hi[0], hi[1], hi[2], hi[3]);
            *(uint4*)&smB[buf][1][woff] = make_uint4(lo[0], lo[1], lo[2], lo[3]);
            __syncthreads();
        }
    }

    // ---- epilogue: write C (+bias). regs: (r,2c),(r,2c+1),(r+8,2c),(r+8,2c+1) ----
    #pragma unroll
    for (int mi = 0; mi < 4; mi++) {
        #pragma unroll
        for (int ni = 0; ni < 4; ni++) {
            const int row = m0 + wm * 64 + mi * 16 + r;
            const int col = n0 + wn * 32 + ni * 8 + c * 2;
            float2 v0 = make_float2(acc[mi][ni][0], acc[mi][ni][1]);
            float2 v1 = make_float2(acc[mi][ni][2], acc[mi][ni][3]);
            if (BIAS) {
                float2 bb = *(const float2*)&bias[col];
                v0.x += bb.x; v0.y += bb.y;
                v1.x += bb.x; v1.y += bb.y;
            }
            *(float2*)&C[(size_t)row * N + col]       = v0;
            *(float2*)&C[(size_t)(row + 8) * N + col] = v1;
        }
    }
}

// ---------------------------------------------------------------------------
// Per-batch transpose: Vt[b][d][n] = V[b][n][d].  32x32 tiles, padded smem.
// ---------------------------------------------------------------------------
__global__ __launch_bounds__(256)
void transposeV(const float* __restrict__ V, float* __restrict__ Vt)
{
    __shared__ float t[32][33];
    const int b  = blockIdx.z;
    const int n0 = blockIdx.x * 32;   // seq
    const int d0 = blockIdx.y * 32;   // dim
    const float* Vb  = V  + (size_t)b * SEQ * DIM;
    float*       Vtb = Vt + (size_t)b * SEQ * DIM;
    const int x = threadIdx.x;

    #pragma unroll
    for (int y = threadIdx.y; y < 32; y += 8)
        t[y][x] = Vb[(size_t)(n0 + y) * DIM + d0 + x];
    __syncthreads();
    #pragma unroll
    for (int y = threadIdx.y; y < 32; y += 8)
        Vtb[(size_t)(d0 + y) * SEQ + n0 + x] = t[x][y];
}

// ---------------------------------------------------------------------------
// Row softmax over rows of length SEQ=2048. One 256-thread block per row.
// Max-subtraction mandatory (unscaled logits, std ~22).
// ---------------------------------------------------------------------------
__global__ __launch_bounds__(256)
void softmax2048(float* __restrict__ S)
{
    __shared__ float sh[8];
    float* p = S + (size_t)blockIdx.x * SEQ;
    const int tid  = threadIdx.x;
    const int lane = tid & 31;
    const int wid  = tid >> 5;

    float4 v0 = ((const float4*)p)[tid];
    float4 v1 = ((const float4*)p)[tid + 256];

    float m = fmaxf(fmaxf(fmaxf(v0.x, v0.y), fmaxf(v0.z, v0.w)),
                    fmaxf(fmaxf(v1.x, v1.y), fmaxf(v1.z, v1.w)));
    #pragma unroll
    for (int o = 16; o > 0; o >>= 1)
        m = fmaxf(m, __shfl_xor_sync(0xffffffffu, m, o));
    if (lane == 0) sh[wid] = m;
    __syncthreads();
    m = sh[0];
    #pragma unroll
    for (int i = 1; i < 8; i++) m = fmaxf(m, sh[i]);
    __syncthreads();

    v0.x = expf(v0.x - m); v0.y = expf(v0.y - m);
    v0.z = expf(v0.z - m); v0.w = expf(v0.w - m);
    v1.x = expf(v1.x - m); v1.y = expf(v1.y - m);
    v1.z = expf(v1.z - m); v1.w = expf(v1.w - m);

    float s = v0.x + v0.y + v0.z + v0.w + v1.x + v1.y + v1.z + v1.w;
    #pragma unroll
    for (int o = 16; o > 0; o >>= 1)
        s += __shfl_xor_sync(0xffffffffu, s, o);
    if (lane == 0) sh[wid] = s;
    __syncthreads();
    s = sh[0] + sh[1] + sh[2] + sh[3] + sh[4] + sh[5] + sh[6] + sh[7];

    const float inv = 1.0f / s;
    v0.x *= inv; v0.y *= inv; v0.z *= inv; v0.w *= inv;
    v1.x *= inv; v1.y *= inv; v1.z *= inv; v1.w *= inv;

    ((float4*)p)[tid]       = v0;
    ((float4*)p)[tid + 256] = v1;
}

extern "C" void kernel_launch(void* const* d_in, const int* in_sizes, int n_in,
                              void* d_out, int out_size)
{
    const float* x  = (const float*)d_in[0];
    const float* Wq = (const float*)d_in[1];
    const float* bq = (const float*)d_in[2];
    const float* Wk = (const float*)d_in[3];
    const float* bk = (const float*)d_in[4];
    const float* Wv = (const float*)d_in[5];
    const float* bv = (const float*)d_in[6];
    float* out = (float*)d_out;

    float *Q, *K, *V, *Vt, *S;
    cudaGetSymbolAddress((void**)&Q,  g_Q);
    cudaGetSymbolAddress((void**)&K,  g_K);
    cudaGetSymbolAddress((void**)&V,  g_V);
    cudaGetSymbolAddress((void**)&Vt, g_Vt);
    cudaGetSymbolAddress((void**)&S,  g_S);

    const dim3 t(256);

    // QKV projections: C[16384,512] = x * W^T + b
    const dim3 gq(DIM / 128, MQKV / 128, 1);
    gemm_bf16c<true ><<<gq, t>>>(x, Wq, bq, Q, MQKV, DIM, DIM, 0, 0, 0);
    gemm_bf16c<true ><<<gq, t>>>(x, Wk, bk, K, MQKV, DIM, DIM, 0, 0, 0);
    gemm_bf16c<true ><<<gq, t>>>(x, Wv, bv, V, MQKV, DIM, DIM, 0, 0, 0);

    // V -> Vt (per batch [DIM, SEQ]) so PV becomes a K-contiguous B^T GEMM
    transposeV<<<dim3(SEQ / 32, DIM / 32, BATCH), dim3(32, 8)>>>(V, Vt);

    // S[b] = Q[b] * K[b]^T : [2048,2048] x 8
    const dim3 gs(SEQ / 128, SEQ / 128, BATCH);
    gemm_bf16c<false><<<gs, t>>>(Q, K, nullptr, S, SEQ, SEQ, DIM,
                                 (size_t)SEQ * DIM, (size_t)SEQ * DIM,
                                 (size_t)SEQ * SEQ);

    // row softmax over keys
    softmax2048<<<BATCH * SEQ, 256>>>(S);

    // O[b] = P[b] * Vt[b]^T : [2048,512] x 8
    const dim3 go(DIM / 128, SEQ / 128, BATCH);
    gemm_bf16c<false><<<go, t>>>(S, Vt, nullptr, out, SEQ, DIM, SEQ,
                                 (size_t)SEQ * SEQ, (size_t)SEQ * DIM,
                                 (size_t)SEQ * DIM);
}